// round 5
// baseline (speedup 1.0000x reference)
#include <cuda_runtime.h>
#include <math.h>

// ---------------- problem constants ----------------
#define BATCH 8
#define CCH   2
#define HF    128
#define INC   512
#define NPTS  128          // N
#define NCAND 384          // 3*N over-generated candidates
#define NIMP  96           // importance points
#define NRAND 16
#define MROWS (BATCH*NPTS) // 1024
#define K1    514          // in_c + C
#define K1P   520          // padded to multiple of 8
#define H1    512
#define H2    256

// ---------------- static scratch (no allocs allowed) ----------------
__device__ float g_points[BATCH*NPTS*2];
__device__ float g_coarse[BATCH*CCH*NPTS];
__device__ float g_buf1 [MROWS*H1];

// order-preserving float -> uint encoding
__device__ __forceinline__ unsigned int fenc(float v) {
    unsigned int u = __float_as_uint(v);
    return (u & 0x80000000u) ? ~u : (u | 0x80000000u);
}

__device__ __forceinline__ float gelu_exact(float y) {
    return 0.5f * y * (1.f + erff(y * 0.70710678118654752f));
}

__device__ __forceinline__ float warp_red(float v) {
    #pragma unroll
    for (int o = 16; o > 0; o >>= 1) v += __shfl_down_sync(0xFFFFFFFFu, v, o);
    return v;  // lane 0 holds sum
}

// =====================================================================
// Kernel 1: sampling-point selection (exact lax.top_k(96) via rank count;
// coverage points provably (0,0); random points appended).
// =====================================================================
__global__ void k_points(const float* __restrict__ out,
                         const float* __restrict__ over_gen,
                         const float* __restrict__ rand_point,
                         float* __restrict__ pts_out, int write_out)
{
    int b = blockIdx.x;
    int t = threadIdx.x;
    __shared__ unsigned long long keys[NCAND];

    if (t < NCAND) {
        float px = over_gen[(b*NCAND + t)*2 + 0];
        float py = over_gen[(b*NCAND + t)*2 + 1];
        float gx = px * HF - 0.5f;
        float gy = py * HF - 0.5f;
        float x0f = floorf(gx), y0f = floorf(gy);
        float wx = gx - x0f, wy = gy - y0f;
        int x0 = (int)x0f, y0 = (int)y0f;
        const float* o0 = out + (size_t)b*CCH*HF*HF;
        const float* o1 = o0 + HF*HF;
        float unc = 0.f;
        #pragma unroll
        for (int dy = 0; dy < 2; dy++) {
            #pragma unroll
            for (int dx = 0; dx < 2; dx++) {
                int xi = x0 + dx, yi = y0 + dy;
                bool valid = (xi >= 0) && (xi < HF) && (yi >= 0) && (yi < HF);
                int xc = min(max(xi, 0), HF-1);
                int yc = min(max(yi, 0), HF-1);
                float a = o0[yc*HF + xc];
                float c = o1[yc*HF + xc];
                float w = (dx ? wx : 1.f - wx) * (dy ? wy : 1.f - wy);
                if (valid) unc += w * (fminf(a, c) - fmaxf(a, c));
            }
        }
        keys[t] = (((unsigned long long)fenc(unc)) << 32)
                | (unsigned long long)(1023 - t);
    }
    __syncthreads();

    if (t < NCAND) {
        unsigned long long mine = keys[t];
        int rank = 0;
        #pragma unroll 8
        for (int j = 0; j < NCAND; j++) rank += (keys[j] > mine);
        if (rank < NIMP) {
            float px = over_gen[(b*NCAND + t)*2 + 0];
            float py = over_gen[(b*NCAND + t)*2 + 1];
            g_points[(b*NPTS + rank)*2 + 0] = px;
            g_points[(b*NPTS + rank)*2 + 1] = py;
            if (write_out) {
                pts_out[(b*NPTS + rank)*2 + 0] = px;
                pts_out[(b*NPTS + rank)*2 + 1] = py;
            }
        }
    }
    if (t < NRAND) {
        int i = NIMP + t;
        int j = NIMP + NRAND + t;
        float rx = rand_point[(b*NRAND + t)*2 + 0];
        float ry = rand_point[(b*NRAND + t)*2 + 1];
        g_points[(b*NPTS + i)*2 + 0] = 0.f;
        g_points[(b*NPTS + i)*2 + 1] = 0.f;
        g_points[(b*NPTS + j)*2 + 0] = rx;
        g_points[(b*NPTS + j)*2 + 1] = ry;
        if (write_out) {
            pts_out[(b*NPTS + i)*2 + 0] = 0.f;
            pts_out[(b*NPTS + i)*2 + 1] = 0.f;
            pts_out[(b*NPTS + j)*2 + 0] = rx;
            pts_out[(b*NPTS + j)*2 + 1] = ry;
        }
    }
}

// =====================================================================
// fgemm1: gather(coarse+fine) -> A[8 x 514], GEMM vs w1[514,512],
// + bias + LayerNorm + GELU -> g_buf1. One block = 8 full output rows.
// Threads 256: tx in [0,128) (TN=4 cols), ty in {0,1} (TM=4 rows).
// =====================================================================
__global__ __launch_bounds__(256)
void fgemm1(const float* __restrict__ res2, const float* __restrict__ out,
            const float* __restrict__ w1, const float* __restrict__ b1,
            const float* __restrict__ gm1, const float* __restrict__ be1)
{
    __shared__ float As[K1P][8];     // [k][row], zero-padded k>=514
    __shared__ float Bs[8][H1];
    __shared__ float Pw[8][4];
    __shared__ int   Pi[8][4];
    __shared__ int   Pb[8];
    __shared__ float red[8][4];

    int tid = threadIdx.x;
    int row0 = blockIdx.x * 8;

    // per-row bilinear params
    if (tid < 8) {
        int row = row0 + tid;
        int b = row >> 7;   // row / NPTS
        float px = g_points[row*2 + 0];
        float py = g_points[row*2 + 1];
        float gx = px*HF - 0.5f, gy = py*HF - 0.5f;
        float x0f = floorf(gx), y0f = floorf(gy);
        float wx = gx - x0f, wy = gy - y0f;
        int x0 = (int)x0f, y0 = (int)y0f;
        int x1 = x0 + 1, y1 = y0 + 1;
        float vx0 = (x0 >= 0 && x0 < HF) ? 1.f : 0.f;
        float vx1 = (x1 >= 0 && x1 < HF) ? 1.f : 0.f;
        float vy0 = (y0 >= 0 && y0 < HF) ? 1.f : 0.f;
        float vy1 = (y1 >= 0 && y1 < HF) ? 1.f : 0.f;
        int xc0 = min(max(x0, 0), HF-1), xc1 = min(max(x1, 0), HF-1);
        int yc0 = min(max(y0, 0), HF-1), yc1 = min(max(y1, 0), HF-1);
        Pw[tid][0] = (1.f-wx)*(1.f-wy)*vx0*vy0;
        Pw[tid][1] = wx*(1.f-wy)*vx1*vy0;
        Pw[tid][2] = (1.f-wx)*wy*vx0*vy1;
        Pw[tid][3] = wx*wy*vx1*vy1;
        Pi[tid][0] = yc0*HF + xc0;  Pi[tid][1] = yc0*HF + xc1;
        Pi[tid][2] = yc1*HF + xc0;  Pi[tid][3] = yc1*HF + xc1;
        Pb[tid] = b;
    }
    __syncthreads();

    // gather A tile (transposed into [k][row])
    #pragma unroll
    for (int r = 0; r < 8; r++) {
        float pw0 = Pw[r][0], pw1 = Pw[r][1], pw2 = Pw[r][2], pw3 = Pw[r][3];
        int i0 = Pi[r][0], i1 = Pi[r][1], i2 = Pi[r][2], i3 = Pi[r][3];
        int b = Pb[r];
        for (int k = tid; k < K1P; k += 256) {
            float v = 0.f;
            if (k < CCH) {
                const float* p = out + ((size_t)(b*CCH + k))*HF*HF;
                v = pw0*p[i0] + pw1*p[i1] + pw2*p[i2] + pw3*p[i3];
                g_coarse[(b*CCH + k)*NPTS + ((row0 + r) & 127)] = v;
            } else if (k < K1) {
                const float* p = res2 + ((size_t)(b*INC + (k - CCH)))*HF*HF;
                v = pw0*__ldg(p+i0) + pw1*__ldg(p+i1)
                  + pw2*__ldg(p+i2) + pw3*__ldg(p+i3);
            }
            As[k][r] = v;
        }
    }
    __syncthreads();

    int tx = tid & 127, ty = tid >> 7;
    float acc[4][4];
    #pragma unroll
    for (int i = 0; i < 4; i++)
        #pragma unroll
        for (int j = 0; j < 4; j++) acc[i][j] = 0.f;

    for (int k0 = 0; k0 < K1P; k0 += 8) {
        #pragma unroll
        for (int i = 0; i < 4; i++) {
            int idx = tid + i*256;           // 1024 float4s = 8x512 floats
            int kk = idx >> 7;
            int nn = (idx & 127) * 4;
            int gk = k0 + kk;
            float4 v = (gk < K1) ? *(const float4*)&w1[(size_t)gk*H1 + nn]
                                 : make_float4(0.f,0.f,0.f,0.f);
            *(float4*)&Bs[kk][nn] = v;
        }
        __syncthreads();
        #pragma unroll
        for (int kk = 0; kk < 8; kk++) {
            float4 ra = *(const float4*)&As[k0 + kk][ty*4];
            float4 rb = *(const float4*)&Bs[kk][tx*4];
            acc[0][0] += ra.x*rb.x; acc[0][1] += ra.x*rb.y; acc[0][2] += ra.x*rb.z; acc[0][3] += ra.x*rb.w;
            acc[1][0] += ra.y*rb.x; acc[1][1] += ra.y*rb.y; acc[1][2] += ra.y*rb.z; acc[1][3] += ra.y*rb.w;
            acc[2][0] += ra.z*rb.x; acc[2][1] += ra.z*rb.y; acc[2][2] += ra.z*rb.z; acc[2][3] += ra.z*rb.w;
            acc[3][0] += ra.w*rb.x; acc[3][1] += ra.w*rb.y; acc[3][2] += ra.w*rb.z; acc[3][3] += ra.w*rb.w;
        }
        __syncthreads();
    }

    // ---- epilogue: bias + LN + GELU ----
    float4 bb = *(const float4*)&b1[tx*4];
    #pragma unroll
    for (int i = 0; i < 4; i++) {
        acc[i][0] += bb.x; acc[i][1] += bb.y; acc[i][2] += bb.z; acc[i][3] += bb.w;
    }
    int lane = tid & 31, wq = (tid >> 5) & 3;
    float mean[4], inv[4];
    #pragma unroll
    for (int i = 0; i < 4; i++) {
        float s = warp_red(acc[i][0] + acc[i][1] + acc[i][2] + acc[i][3]);
        if (lane == 0) red[ty*4 + i][wq] = s;
    }
    __syncthreads();
    #pragma unroll
    for (int i = 0; i < 4; i++) {
        int r = ty*4 + i;
        mean[i] = (red[r][0] + red[r][1] + red[r][2] + red[r][3]) * (1.f/H1);
    }
    __syncthreads();
    #pragma unroll
    for (int i = 0; i < 4; i++) {
        float d0 = acc[i][0]-mean[i], d1 = acc[i][1]-mean[i];
        float d2 = acc[i][2]-mean[i], d3 = acc[i][3]-mean[i];
        float s = warp_red(d0*d0 + d1*d1 + d2*d2 + d3*d3);
        if (lane == 0) red[ty*4 + i][wq] = s;
    }
    __syncthreads();
    #pragma unroll
    for (int i = 0; i < 4; i++) {
        int r = ty*4 + i;
        float var = (red[r][0] + red[r][1] + red[r][2] + red[r][3]) * (1.f/H1);
        inv[i] = rsqrtf(var + 1e-5f);
    }
    float4 gg = *(const float4*)&gm1[tx*4];
    float4 be = *(const float4*)&be1[tx*4];
    #pragma unroll
    for (int i = 0; i < 4; i++) {
        int row = row0 + ty*4 + i;
        float4 o;
        o.x = gelu_exact((acc[i][0]-mean[i])*inv[i]*gg.x + be.x);
        o.y = gelu_exact((acc[i][1]-mean[i])*inv[i]*gg.y + be.y);
        o.z = gelu_exact((acc[i][2]-mean[i])*inv[i]*gg.z + be.z);
        o.w = gelu_exact((acc[i][3]-mean[i])*inv[i]*gg.w + be.w);
        *(float4*)&g_buf1[(size_t)row*H1 + tx*4] = o;
    }
}

// =====================================================================
// fgemm2: GEMM [8x512]@[512,256] + bias + LN + GELU + (h@w3+b3) dot
// + dropout mask + coarse residual -> rend. One block = 8 output rows.
// Threads 128: tx in [0,64) (TN=4), ty in {0,1} (TM=4).
// =====================================================================
__global__ __launch_bounds__(128)
void fgemm2(const float* __restrict__ w2, const float* __restrict__ b2,
            const float* __restrict__ gm2, const float* __restrict__ be2,
            const float* __restrict__ w3, const float* __restrict__ b3,
            const float* __restrict__ mask, float* __restrict__ rend)
{
    __shared__ float As[H1][8];
    __shared__ float Bs[8][H2];
    __shared__ float red[8][2];
    __shared__ float rp0[8][2], rp1[8][2];

    int tid = threadIdx.x;
    int row0 = blockIdx.x * 8;

    #pragma unroll
    for (int r = 0; r < 8; r++)
        for (int k = tid; k < H1; k += 128)
            As[k][r] = g_buf1[(size_t)(row0 + r)*H1 + k];
    __syncthreads();

    int tx = tid & 63, ty = tid >> 6;
    float acc[4][4];
    #pragma unroll
    for (int i = 0; i < 4; i++)
        #pragma unroll
        for (int j = 0; j < 4; j++) acc[i][j] = 0.f;

    for (int k0 = 0; k0 < H1; k0 += 8) {
        #pragma unroll
        for (int i = 0; i < 4; i++) {
            int idx = tid + i*128;           // 512 float4s = 8x256 floats
            int kk = idx >> 6;
            int nn = (idx & 63) * 4;
            *(float4*)&Bs[kk][nn] = *(const float4*)&w2[(size_t)(k0+kk)*H2 + nn];
        }
        __syncthreads();
        #pragma unroll
        for (int kk = 0; kk < 8; kk++) {
            float4 ra = *(const float4*)&As[k0 + kk][ty*4];
            float4 rb = *(const float4*)&Bs[kk][tx*4];
            acc[0][0] += ra.x*rb.x; acc[0][1] += ra.x*rb.y; acc[0][2] += ra.x*rb.z; acc[0][3] += ra.x*rb.w;
            acc[1][0] += ra.y*rb.x; acc[1][1] += ra.y*rb.y; acc[1][2] += ra.y*rb.z; acc[1][3] += ra.y*rb.w;
            acc[2][0] += ra.z*rb.x; acc[2][1] += ra.z*rb.y; acc[2][2] += ra.z*rb.z; acc[2][3] += ra.z*rb.w;
            acc[3][0] += ra.w*rb.x; acc[3][1] += ra.w*rb.y; acc[3][2] += ra.w*rb.z; acc[3][3] += ra.w*rb.w;
        }
        __syncthreads();
    }

    // ---- epilogue: bias + LN + GELU + final projection + residual ----
    float4 bb = *(const float4*)&b2[tx*4];
    #pragma unroll
    for (int i = 0; i < 4; i++) {
        acc[i][0] += bb.x; acc[i][1] += bb.y; acc[i][2] += bb.z; acc[i][3] += bb.w;
    }
    int lane = tid & 31, wh = (tid >> 5) & 1;
    float mean[4], inv[4];
    #pragma unroll
    for (int i = 0; i < 4; i++) {
        float s = warp_red(acc[i][0] + acc[i][1] + acc[i][2] + acc[i][3]);
        if (lane == 0) red[ty*4 + i][wh] = s;
    }
    __syncthreads();
    #pragma unroll
    for (int i = 0; i < 4; i++)
        mean[i] = (red[ty*4+i][0] + red[ty*4+i][1]) * (1.f/H2);
    __syncthreads();
    #pragma unroll
    for (int i = 0; i < 4; i++) {
        float d0 = acc[i][0]-mean[i], d1 = acc[i][1]-mean[i];
        float d2 = acc[i][2]-mean[i], d3 = acc[i][3]-mean[i];
        float s = warp_red(d0*d0 + d1*d1 + d2*d2 + d3*d3);
        if (lane == 0) red[ty*4 + i][wh] = s;
    }
    __syncthreads();
    #pragma unroll
    for (int i = 0; i < 4; i++) {
        float var = (red[ty*4+i][0] + red[ty*4+i][1]) * (1.f/H2);
        inv[i] = rsqrtf(var + 1e-5f);
    }
    float4 gg = *(const float4*)&gm2[tx*4];
    float4 be = *(const float4*)&be2[tx*4];
    float w30[4], w31[4];
    #pragma unroll
    for (int j = 0; j < 4; j++) {
        int c = tx*4 + j;
        w30[j] = w3[c*2 + 0];
        w31[j] = w3[c*2 + 1];
    }
    #pragma unroll
    for (int i = 0; i < 4; i++) {
        float h0 = gelu_exact((acc[i][0]-mean[i])*inv[i]*gg.x + be.x);
        float h1 = gelu_exact((acc[i][1]-mean[i])*inv[i]*gg.y + be.y);
        float h2 = gelu_exact((acc[i][2]-mean[i])*inv[i]*gg.z + be.z);
        float h3 = gelu_exact((acc[i][3]-mean[i])*inv[i]*gg.w + be.w);
        float p0 = warp_red(h0*w30[0] + h1*w30[1] + h2*w30[2] + h3*w30[3]);
        float p1 = warp_red(h0*w31[0] + h1*w31[1] + h2*w31[2] + h3*w31[3]);
        if (lane == 0) { rp0[ty*4+i][wh] = p0; rp1[ty*4+i][wh] = p1; }
    }
    __syncthreads();
    if (tid < 8) {
        int rg = row0 + tid;
        int b = rg >> 7, n = rg & 127;
        int i0 = (b*CCH + 0)*NPTS + n;
        int i1 = (b*CCH + 1)*NPTS + n;
        float p0 = rp0[tid][0] + rp0[tid][1] + b3[0];
        float p1 = rp1[tid][0] + rp1[tid][1] + b3[1];
        rend[i0] = p0 * mask[i0] + g_coarse[i0];
        rend[i1] = p1 * mask[i1] + g_coarse[i1];
    }
}

// =====================================================================
extern "C" void kernel_launch(void* const* d_in, const int* in_sizes, int n_in,
                              void* d_out, int out_size)
{
    // metadata order: x, res2, out, over_gen, rand_point, dropout_mask,
    //                 w1,b1,g1,be1, w2,b2,g2,be2, w3,b3
    const float* res2       = (const float*)d_in[1];
    const float* out        = (const float*)d_in[2];
    const float* over_gen   = (const float*)d_in[3];
    const float* rand_point = (const float*)d_in[4];
    const float* mask       = (const float*)d_in[5];
    const float* w1  = (const float*)d_in[6];
    const float* b1  = (const float*)d_in[7];
    const float* gm1 = (const float*)d_in[8];
    const float* be1 = (const float*)d_in[9];
    const float* w2  = (const float*)d_in[10];
    const float* b2  = (const float*)d_in[11];
    const float* gm2 = (const float*)d_in[12];
    const float* be2 = (const float*)d_in[13];
    const float* w3  = (const float*)d_in[14];
    const float* b3  = (const float*)d_in[15];

    float* rend = (float*)d_out;
    int has_pts = (out_size >= BATCH*CCH*NPTS + BATCH*NPTS*2) ? 1 : 0;
    float* pts  = rend + BATCH*CCH*NPTS;

    k_points<<<BATCH, NCAND>>>(out, over_gen, rand_point, pts, has_pts);
    fgemm1<<<MROWS/8, 256>>>(res2, out, w1, b1, gm1, be1);
    fgemm2<<<MROWS/8, 128>>>(w2, b2, gm2, be2, w3, b3, mask, rend);
}

// round 6
// speedup vs baseline: 1.9019x; 1.9019x over previous
#include <cuda_runtime.h>
#include <math.h>

// ---------------- problem constants ----------------
#define BATCH 8
#define CCH   2
#define HF    128
#define INC   512
#define NPTS  128          // N
#define NCAND 384
#define NIMP  96
#define NRAND 16
#define MROWS (BATCH*NPTS) // 1024
#define K1    514          // in_c + C
#define K1P   528          // padded to multiple of 16
#define H1    512
#define H2    256

// ---------------- static scratch ----------------
__device__ float g_points[BATCH*NPTS*2];
__device__ float g_coarse[BATCH*CCH*NPTS];
__device__ float g_feat [MROWS*K1P];
__device__ float g_buf1 [MROWS*H1];
__device__ float g_buf2 [MROWS*H2];

__device__ __forceinline__ unsigned int fenc(float v) {
    unsigned int u = __float_as_uint(v);
    return (u & 0x80000000u) ? ~u : (u | 0x80000000u);
}
__device__ __forceinline__ float gelu_exact(float y) {
    return 0.5f * y * (1.f + erff(y * 0.70710678118654752f));
}
__device__ __forceinline__ float warp_allred(float v) {
    #pragma unroll
    for (int o = 16; o > 0; o >>= 1) v += __shfl_xor_sync(0xFFFFFFFFu, v, o);
    return v;
}

// =====================================================================
// Kernel 1: sampling-point selection (exact lax.top_k(96) via rank count;
// coverage points provably (0,0); random points appended).
// =====================================================================
__global__ void k_points(const float* __restrict__ out,
                         const float* __restrict__ over_gen,
                         const float* __restrict__ rand_point,
                         float* __restrict__ pts_out, int write_out)
{
    int b = blockIdx.x;
    int t = threadIdx.x;
    __shared__ unsigned long long keys[NCAND];

    if (t < NCAND) {
        float px = over_gen[(b*NCAND + t)*2 + 0];
        float py = over_gen[(b*NCAND + t)*2 + 1];
        float gx = px * HF - 0.5f;
        float gy = py * HF - 0.5f;
        float x0f = floorf(gx), y0f = floorf(gy);
        float wx = gx - x0f, wy = gy - y0f;
        int x0 = (int)x0f, y0 = (int)y0f;
        const float* o0 = out + (size_t)b*CCH*HF*HF;
        const float* o1 = o0 + HF*HF;
        float unc = 0.f;
        #pragma unroll
        for (int dy = 0; dy < 2; dy++) {
            #pragma unroll
            for (int dx = 0; dx < 2; dx++) {
                int xi = x0 + dx, yi = y0 + dy;
                bool valid = (xi >= 0) && (xi < HF) && (yi >= 0) && (yi < HF);
                int xc = min(max(xi, 0), HF-1);
                int yc = min(max(yi, 0), HF-1);
                float a = o0[yc*HF + xc];
                float c = o1[yc*HF + xc];
                float w = (dx ? wx : 1.f - wx) * (dy ? wy : 1.f - wy);
                if (valid) unc += w * (fminf(a, c) - fmaxf(a, c));
            }
        }
        keys[t] = (((unsigned long long)fenc(unc)) << 32)
                | (unsigned long long)(1023 - t);
    }
    __syncthreads();

    if (t < NCAND) {
        unsigned long long mine = keys[t];
        int rank = 0;
        #pragma unroll 8
        for (int j = 0; j < NCAND; j++) rank += (keys[j] > mine);
        if (rank < NIMP) {
            float px = over_gen[(b*NCAND + t)*2 + 0];
            float py = over_gen[(b*NCAND + t)*2 + 1];
            g_points[(b*NPTS + rank)*2 + 0] = px;
            g_points[(b*NPTS + rank)*2 + 1] = py;
            if (write_out) {
                pts_out[(b*NPTS + rank)*2 + 0] = px;
                pts_out[(b*NPTS + rank)*2 + 1] = py;
            }
        }
    }
    if (t < NRAND) {
        int i = NIMP + t;
        int j = NIMP + NRAND + t;
        float rx = rand_point[(b*NRAND + t)*2 + 0];
        float ry = rand_point[(b*NRAND + t)*2 + 1];
        g_points[(b*NPTS + i)*2 + 0] = 0.f;
        g_points[(b*NPTS + i)*2 + 1] = 0.f;
        g_points[(b*NPTS + j)*2 + 0] = rx;
        g_points[(b*NPTS + j)*2 + 1] = ry;
        if (write_out) {
            pts_out[(b*NPTS + i)*2 + 0] = 0.f;
            pts_out[(b*NPTS + i)*2 + 1] = 0.f;
            pts_out[(b*NPTS + j)*2 + 0] = rx;
            pts_out[(b*NPTS + j)*2 + 1] = ry;
        }
    }
}

// =====================================================================
// Kernel 2: bilinear gather -> g_feat row [coarse(2) | fine(512) | pad0],
// row-major padded to K1P. One block per (b,n).
// =====================================================================
__global__ void k_gather(const float* __restrict__ res2,
                         const float* __restrict__ out)
{
    int n = blockIdx.x, b = blockIdx.y;
    int row = b*NPTS + n;
    float px = g_points[row*2 + 0];
    float py = g_points[row*2 + 1];
    float gx = px*HF - 0.5f, gy = py*HF - 0.5f;
    float x0f = floorf(gx), y0f = floorf(gy);
    float wx = gx - x0f, wy = gy - y0f;
    int x0 = (int)x0f, y0 = (int)y0f;
    int x1 = x0 + 1, y1 = y0 + 1;
    float vx0 = (x0 >= 0 && x0 < HF) ? 1.f : 0.f;
    float vx1 = (x1 >= 0 && x1 < HF) ? 1.f : 0.f;
    float vy0 = (y0 >= 0 && y0 < HF) ? 1.f : 0.f;
    float vy1 = (y1 >= 0 && y1 < HF) ? 1.f : 0.f;
    int xc0 = min(max(x0, 0), HF-1), xc1 = min(max(x1, 0), HF-1);
    int yc0 = min(max(y0, 0), HF-1), yc1 = min(max(y1, 0), HF-1);
    float w00 = (1.f-wx)*(1.f-wy)*vx0*vy0;
    float w10 = wx*(1.f-wy)*vx1*vy0;
    float w01 = (1.f-wx)*wy*vx0*vy1;
    float w11 = wx*wy*vx1*vy1;
    int i00 = yc0*HF + xc0, i10 = yc0*HF + xc1;
    int i01 = yc1*HF + xc0, i11 = yc1*HF + xc1;

    for (int k = threadIdx.x; k < K1P; k += blockDim.x) {
        float v = 0.f;
        if (k < CCH) {
            const float* p = out + ((size_t)(b*CCH + k))*HF*HF;
            v = w00*p[i00] + w10*p[i10] + w01*p[i01] + w11*p[i11];
            g_coarse[(b*CCH + k)*NPTS + n] = v;
        } else if (k < K1) {
            const float* p = res2 + ((size_t)(b*INC + (k - CCH)))*HF*HF;
            v = w00*__ldg(p+i00) + w10*__ldg(p+i10)
              + w01*__ldg(p+i01) + w11*__ldg(p+i11);
        }
        g_feat[(size_t)row*K1P + k] = v;
    }
}

// =====================================================================
// GEMM1: C[1024,512] = feat[1024,528(514)] @ w1[514,512] + b1
// 64x64x16 tiles, 256 threads, TM=TN=4, vectorized global ld/st.
// =====================================================================
__global__ __launch_bounds__(256)
void sgemm1(const float* __restrict__ A, const float* __restrict__ B,
            const float* __restrict__ bias, float* __restrict__ C)
{
    __shared__ float As[16][65];
    __shared__ float Bs[16][64];
    int tid = threadIdx.x;
    int bm = blockIdx.y * 64, bn = blockIdx.x * 64;
    int tx = tid & 15, ty = tid >> 4;

    // A-load mapping: thread -> (m = tid/4, kq = tid%4) loads float4
    int am = tid >> 2, akq = (tid & 3) << 2;
    // B-load mapping: thread -> (kk = tid/16, nq = tid%16) loads float4
    int bkk = tid >> 4, bnq = (tid & 15) << 2;

    float acc[4][4];
    #pragma unroll
    for (int i = 0; i < 4; i++)
        #pragma unroll
        for (int j = 0; j < 4; j++) acc[i][j] = 0.f;

    for (int k0 = 0; k0 < K1P; k0 += 16) {
        float4 av = *(const float4*)&A[(size_t)(bm + am)*K1P + k0 + akq];
        int gk = k0 + bkk;
        float4 bv = (gk < K1) ? *(const float4*)&B[(size_t)gk*H1 + bn + bnq]
                              : make_float4(0.f,0.f,0.f,0.f);
        As[akq+0][am] = av.x; As[akq+1][am] = av.y;
        As[akq+2][am] = av.z; As[akq+3][am] = av.w;
        *(float4*)&Bs[bkk][bnq] = bv;
        __syncthreads();
        #pragma unroll
        for (int kk = 0; kk < 16; kk++) {
            float ra0 = As[kk][ty*4+0], ra1 = As[kk][ty*4+1];
            float ra2 = As[kk][ty*4+2], ra3 = As[kk][ty*4+3];
            float4 rb = *(const float4*)&Bs[kk][tx*4];
            acc[0][0] += ra0*rb.x; acc[0][1] += ra0*rb.y; acc[0][2] += ra0*rb.z; acc[0][3] += ra0*rb.w;
            acc[1][0] += ra1*rb.x; acc[1][1] += ra1*rb.y; acc[1][2] += ra1*rb.z; acc[1][3] += ra1*rb.w;
            acc[2][0] += ra2*rb.x; acc[2][1] += ra2*rb.y; acc[2][2] += ra2*rb.z; acc[2][3] += ra2*rb.w;
            acc[3][0] += ra3*rb.x; acc[3][1] += ra3*rb.y; acc[3][2] += ra3*rb.z; acc[3][3] += ra3*rb.w;
        }
        __syncthreads();
    }
    float4 bb = *(const float4*)&bias[bn + tx*4];
    #pragma unroll
    for (int i = 0; i < 4; i++) {
        int m = bm + ty*4 + i;
        float4 o;
        o.x = acc[i][0] + bb.x; o.y = acc[i][1] + bb.y;
        o.z = acc[i][2] + bb.z; o.w = acc[i][3] + bb.w;
        *(float4*)&C[(size_t)m*H1 + bn + tx*4] = o;
    }
}

// =====================================================================
// GEMM2: C[1024,256] = buf1[1024,512] @ w2[512,256] + b2
// 32x64x16 tiles, 256 threads, TM=2 TN=4.
// =====================================================================
__global__ __launch_bounds__(256)
void sgemm2(const float* __restrict__ A, const float* __restrict__ B,
            const float* __restrict__ bias, float* __restrict__ C)
{
    __shared__ float As[16][33];
    __shared__ float Bs[16][64];
    int tid = threadIdx.x;
    int bm = blockIdx.y * 32, bn = blockIdx.x * 64;
    int tx = tid & 15, ty = tid >> 4;

    int am = tid >> 2, akq = (tid & 3) << 2;   // threads <128 load A
    int bkk = tid >> 4, bnq = (tid & 15) << 2;

    float acc[2][4];
    #pragma unroll
    for (int i = 0; i < 2; i++)
        #pragma unroll
        for (int j = 0; j < 4; j++) acc[i][j] = 0.f;

    for (int k0 = 0; k0 < H1; k0 += 16) {
        if (tid < 128) {
            float4 av = *(const float4*)&A[(size_t)(bm + am)*H1 + k0 + akq];
            As[akq+0][am] = av.x; As[akq+1][am] = av.y;
            As[akq+2][am] = av.z; As[akq+3][am] = av.w;
        }
        *(float4*)&Bs[bkk][bnq] = *(const float4*)&B[(size_t)(k0 + bkk)*H2 + bn + bnq];
        __syncthreads();
        #pragma unroll
        for (int kk = 0; kk < 16; kk++) {
            float ra0 = As[kk][ty*2+0], ra1 = As[kk][ty*2+1];
            float4 rb = *(const float4*)&Bs[kk][tx*4];
            acc[0][0] += ra0*rb.x; acc[0][1] += ra0*rb.y; acc[0][2] += ra0*rb.z; acc[0][3] += ra0*rb.w;
            acc[1][0] += ra1*rb.x; acc[1][1] += ra1*rb.y; acc[1][2] += ra1*rb.z; acc[1][3] += ra1*rb.w;
        }
        __syncthreads();
    }
    float4 bb = *(const float4*)&bias[bn + tx*4];
    #pragma unroll
    for (int i = 0; i < 2; i++) {
        int m = bm + ty*2 + i;
        float4 o;
        o.x = acc[i][0] + bb.x; o.y = acc[i][1] + bb.y;
        o.z = acc[i][2] + bb.z; o.w = acc[i][3] + bb.w;
        *(float4*)&C[(size_t)m*H2 + bn + tx*4] = o;
    }
}

// =====================================================================
// LN+GELU, warp-per-row, D=512: 16 floats/thread, no smem, no barriers.
// =====================================================================
__global__ __launch_bounds__(256)
void ln_gelu_warp512(float* __restrict__ X,
                     const float* __restrict__ gw, const float* __restrict__ bw)
{
    int warp = threadIdx.x >> 5, lane = threadIdx.x & 31;
    int row = blockIdx.x * 8 + warp;
    float* x = X + (size_t)row * H1;
    float4 v[4];
    float s = 0.f;
    #pragma unroll
    for (int i = 0; i < 4; i++) {
        v[i] = *(const float4*)&x[i*128 + lane*4];
        s += v[i].x + v[i].y + v[i].z + v[i].w;
    }
    float mean = warp_allred(s) * (1.f/H1);
    float s2 = 0.f;
    #pragma unroll
    for (int i = 0; i < 4; i++) {
        float d0 = v[i].x-mean, d1 = v[i].y-mean, d2 = v[i].z-mean, d3 = v[i].w-mean;
        s2 += d0*d0 + d1*d1 + d2*d2 + d3*d3;
    }
    float inv = rsqrtf(warp_allred(s2) * (1.f/H1) + 1e-5f);
    #pragma unroll
    for (int i = 0; i < 4; i++) {
        float4 g = *(const float4*)&gw[i*128 + lane*4];
        float4 b = *(const float4*)&bw[i*128 + lane*4];
        float4 o;
        o.x = gelu_exact((v[i].x-mean)*inv*g.x + b.x);
        o.y = gelu_exact((v[i].y-mean)*inv*g.y + b.y);
        o.z = gelu_exact((v[i].z-mean)*inv*g.z + b.z);
        o.w = gelu_exact((v[i].w-mean)*inv*g.w + b.w);
        *(float4*)&x[i*128 + lane*4] = o;
    }
}

// =====================================================================
// LN+GELU (D=256) + final projection (256->2) + dropout + coarse residual,
// warp-per-row. 8 floats/thread.
// =====================================================================
__global__ __launch_bounds__(256)
void ln_final(const float* __restrict__ gw, const float* __restrict__ bw,
              const float* __restrict__ w3, const float* __restrict__ b3,
              const float* __restrict__ mask, float* __restrict__ rend)
{
    int warp = threadIdx.x >> 5, lane = threadIdx.x & 31;
    int row = blockIdx.x * 8 + warp;
    const float* x = g_buf2 + (size_t)row * H2;
    float4 v[2];
    float s = 0.f;
    #pragma unroll
    for (int i = 0; i < 2; i++) {
        v[i] = *(const float4*)&x[i*128 + lane*4];
        s += v[i].x + v[i].y + v[i].z + v[i].w;
    }
    float mean = warp_allred(s) * (1.f/H2);
    float s2 = 0.f;
    #pragma unroll
    for (int i = 0; i < 2; i++) {
        float d0 = v[i].x-mean, d1 = v[i].y-mean, d2 = v[i].z-mean, d3 = v[i].w-mean;
        s2 += d0*d0 + d1*d1 + d2*d2 + d3*d3;
    }
    float inv = rsqrtf(warp_allred(s2) * (1.f/H2) + 1e-5f);
    float p0 = 0.f, p1 = 0.f;
    #pragma unroll
    for (int i = 0; i < 2; i++) {
        int c = i*128 + lane*4;
        float4 g = *(const float4*)&gw[c];
        float4 b = *(const float4*)&bw[c];
        float h0 = gelu_exact((v[i].x-mean)*inv*g.x + b.x);
        float h1 = gelu_exact((v[i].y-mean)*inv*g.y + b.y);
        float h2 = gelu_exact((v[i].z-mean)*inv*g.z + b.z);
        float h3 = gelu_exact((v[i].w-mean)*inv*g.w + b.w);
        float4 wA = *(const float4*)&w3[c*2];       // (w3[c][0],w3[c][1],w3[c+1][0],w3[c+1][1])
        float4 wB = *(const float4*)&w3[c*2 + 4];
        p0 += h0*wA.x + h1*wA.z + h2*wB.x + h3*wB.z;
        p1 += h0*wA.y + h1*wA.w + h2*wB.y + h3*wB.w;
    }
    p0 = warp_allred(p0);
    p1 = warp_allred(p1);
    if (lane == 0) {
        int b = row >> 7, n = row & 127;
        int i0 = (b*CCH + 0)*NPTS + n;
        int i1 = (b*CCH + 1)*NPTS + n;
        rend[i0] = (p0 + b3[0]) * mask[i0] + g_coarse[i0];
        rend[i1] = (p1 + b3[1]) * mask[i1] + g_coarse[i1];
    }
}

// =====================================================================
extern "C" void kernel_launch(void* const* d_in, const int* in_sizes, int n_in,
                              void* d_out, int out_size)
{
    const float* res2       = (const float*)d_in[1];
    const float* out        = (const float*)d_in[2];
    const float* over_gen   = (const float*)d_in[3];
    const float* rand_point = (const float*)d_in[4];
    const float* mask       = (const float*)d_in[5];
    const float* w1  = (const float*)d_in[6];
    const float* b1  = (const float*)d_in[7];
    const float* gm1 = (const float*)d_in[8];
    const float* be1 = (const float*)d_in[9];
    const float* w2  = (const float*)d_in[10];
    const float* b2  = (const float*)d_in[11];
    const float* gm2 = (const float*)d_in[12];
    const float* be2 = (const float*)d_in[13];
    const float* w3  = (const float*)d_in[14];
    const float* b3  = (const float*)d_in[15];

    float* rend = (float*)d_out;
    int has_pts = (out_size >= BATCH*CCH*NPTS + BATCH*NPTS*2) ? 1 : 0;
    float* pts  = rend + BATCH*CCH*NPTS;

    float *p_feat, *p_buf1, *p_buf2;
    cudaGetSymbolAddress((void**)&p_feat, g_feat);
    cudaGetSymbolAddress((void**)&p_buf1, g_buf1);
    cudaGetSymbolAddress((void**)&p_buf2, g_buf2);

    k_points<<<BATCH, NCAND>>>(out, over_gen, rand_point, pts, has_pts);

    dim3 gg(NPTS, BATCH);
    k_gather<<<gg, 256>>>(res2, out);

    {   // [1024,528]@[514->512,512]
        dim3 grid(H1/64, MROWS/64);
        sgemm1<<<grid, 256>>>(p_feat, w1, b1, p_buf1);
    }
    ln_gelu_warp512<<<MROWS/8, 256>>>(p_buf1, gm1, be1);

    {   // [1024,512]@[512,256]
        dim3 grid(H2/64, MROWS/32);
        sgemm2<<<grid, 256>>>(p_buf1, w2, b2, p_buf2);
    }
    ln_final<<<MROWS/8, 256>>>(gm2, be2, w3, b3, mask, rend);
}